// round 2
// baseline (speedup 1.0000x reference)
#include <cuda_runtime.h>

// Problem constants
#define CD   1024          // C
#define NTOK 2048          // per-batch tokens (excluding class token)
#define BB   8             // batch
#define SCALE 0.0625f      // Dh^-0.5 = 1/16

// Scratch (static device globals; allocation-free)
__device__ float g_q0p[32 * 1024];        // q0 partials [cchunk][j]
__device__ float g_wk[4 * 1024];          // per-head score vectors (scaled by 1/16)
__device__ float g_party[128 * 4 * 1024]; // flash partial y [blk][h][c]
__device__ float g_partm[128 * 4];        // flash partial max
__device__ float g_partz[128 * 4];        // flash partial Z
__device__ float g_ybar[8 * 4 * 1024];    // normalized att-weighted x rows
__device__ float g_p1[8 * 8 * 1024];      // gemv1 partials [cchunk][b][j]
__device__ float g_p2[8 * 8 * 1024];      // gemv2 partials [ichunk][b][j]

// ---------------------------------------------------------------------------
// K_A: q0 partials. q0[j] = sum_c tmp[c] * Wqkv[c][j]  (bias added in K_B)
// grid 32 (c-chunks of 32), 256 threads
__global__ void k_q0_part(const float* __restrict__ tmp,
                          const float* __restrict__ Wqkv) {
    int cc  = blockIdx.x;
    int tid = threadIdx.x;
    float acc0 = 0.f, acc1 = 0.f, acc2 = 0.f, acc3 = 0.f;
    for (int r = 0; r < 32; ++r) {
        int c = cc * 32 + r;
        float tv = tmp[c];
        const float* row = Wqkv + (size_t)c * 3072;
        acc0 += tv * row[0 * 256 + tid];
        acc1 += tv * row[1 * 256 + tid];
        acc2 += tv * row[2 * 256 + tid];
        acc3 += tv * row[3 * 256 + tid];
    }
    g_q0p[cc * 1024 + 0 * 256 + tid] = acc0;
    g_q0p[cc * 1024 + 1 * 256 + tid] = acc1;
    g_q0p[cc * 1024 + 2 * 256 + tid] = acc2;
    g_q0p[cc * 1024 + 3 * 256 + tid] = acc3;
}

// ---------------------------------------------------------------------------
// K_B: reduce q0 (+bias) in smem, then wk_h[c] = (1/16) * sum_d Wk[c][h*256+d]*q0[h*256+d]
// grid 128 (8 c-rows per block, one per warp), 256 threads
__global__ void k_wk(const float* __restrict__ Wqkv,
                     const float* __restrict__ bqkv) {
    __shared__ float q0_s[1024];
    int tid = threadIdx.x;
    #pragma unroll
    for (int jj = 0; jj < 4; ++jj) {
        int j = jj * 256 + tid;
        float v = bqkv[j];
        #pragma unroll
        for (int cc = 0; cc < 32; ++cc) v += g_q0p[cc * 1024 + j];
        q0_s[j] = v;
    }
    __syncthreads();
    int warp = tid >> 5, lane = tid & 31;
    int c = blockIdx.x * 8 + warp;
    const float* wrow = Wqkv + (size_t)c * 3072 + 1024;
    float acc[4] = {0.f, 0.f, 0.f, 0.f};
    #pragma unroll
    for (int q = 0; q < 32; ++q) {
        int j = q * 32 + lane;
        acc[q >> 3] += wrow[j] * q0_s[j];
    }
    #pragma unroll
    for (int h = 0; h < 4; ++h) {
        float v = acc[h];
        v += __shfl_xor_sync(0xffffffffu, v, 1);
        v += __shfl_xor_sync(0xffffffffu, v, 2);
        v += __shfl_xor_sync(0xffffffffu, v, 4);
        v += __shfl_xor_sync(0xffffffffu, v, 8);
        v += __shfl_xor_sync(0xffffffffu, v, 16);
        if (lane == 0) g_wk[h * 1024 + c] = v * SCALE;
    }
}

// ---------------------------------------------------------------------------
// K_C: flash pass over x. Per block: one (batch, 128-token chunk).
// Thread t: head h = t&3, c-slice cs = t>>2 (16 floats). wk register-resident.
// Processes 8 tokens per super-iteration (online softmax managed by threads 0..3).
__global__ __launch_bounds__(256) void k_flash(const float* __restrict__ x) {
    __shared__ float4 xs4[8 * 256];   // 8 token rows x 1024 floats
    __shared__ float  ps[8][4][8];    // per-warp partial scores [warp][h][tt]
    __shared__ float  ss[8][4];       // scores [tt][h]
    __shared__ float  wws[8][4];      // exp weights [tt][h]
    __shared__ float  fct[4];         // rescale factor per head

    int tid  = threadIdx.x;
    int b    = blockIdx.y, chunk = blockIdx.x;
    int h    = tid & 3, cs = tid >> 2;
    int warp = tid >> 5, lane = tid & 31;

    float wkr[16];
    #pragma unroll
    for (int k = 0; k < 16; ++k) wkr[k] = g_wk[h * 1024 + cs * 16 + k];
    float y[16];
    #pragma unroll
    for (int k = 0; k < 16; ++k) y[k] = 0.f;
    float m = -1e30f, Z = 0.f;  // only meaningful for tid<4 (managers)

    const float4* xbase = (const float4*)(x + ((size_t)b * NTOK + (size_t)chunk * 128) * CD);

    for (int it = 0; it < 16; ++it) {
        __syncthreads();  // previous phase-2 reads of xs4 complete
        const float4* src = xbase + it * 8 * 256;
        #pragma unroll
        for (int r = 0; r < 8; ++r) xs4[r * 256 + tid] = src[r * 256 + tid];
        __syncthreads();

        // phase 1: partial dots for 8 tokens, my head, my 16-c slice
        float p[8];
        #pragma unroll
        for (int tt = 0; tt < 8; ++tt) {
            const float4* xr = &xs4[tt * 256 + cs * 4];
            float4 a0 = xr[0], a1 = xr[1], a2 = xr[2], a3 = xr[3];
            p[tt] = a0.x*wkr[0]  + a0.y*wkr[1]  + a0.z*wkr[2]  + a0.w*wkr[3]
                  + a1.x*wkr[4]  + a1.y*wkr[5]  + a1.z*wkr[6]  + a1.w*wkr[7]
                  + a2.x*wkr[8]  + a2.y*wkr[9]  + a2.z*wkr[10] + a2.w*wkr[11]
                  + a3.x*wkr[12] + a3.y*wkr[13] + a3.z*wkr[14] + a3.w*wkr[15];
        }
        // reduce over cs within warp (lanes sharing h: xor 4,8,16)
        #pragma unroll
        for (int tt = 0; tt < 8; ++tt) {
            p[tt] += __shfl_xor_sync(0xffffffffu, p[tt], 4);
            p[tt] += __shfl_xor_sync(0xffffffffu, p[tt], 8);
            p[tt] += __shfl_xor_sync(0xffffffffu, p[tt], 16);
        }
        if (lane < 4) {
            #pragma unroll
            for (int tt = 0; tt < 8; ++tt) ps[warp][lane][tt] = p[tt];
        }
        __syncthreads();
        // cross-warp reduce: 32 threads cover (h, tt)
        if (tid < 32) {
            int th = tid & 3, ttt = tid >> 2;
            float s = 0.f;
            #pragma unroll
            for (int w2 = 0; w2 < 8; ++w2) s += ps[w2][th][ttt];
            ss[ttt][th] = s;
        }
        __syncthreads();
        // softmax managers (thread tid = head tid)
        if (tid < 4) {
            float mloc = m;
            #pragma unroll
            for (int tt = 0; tt < 8; ++tt) mloc = fmaxf(mloc, ss[tt][tid]);
            float f = __expf(m - mloc);
            float zadd = 0.f;
            #pragma unroll
            for (int tt = 0; tt < 8; ++tt) {
                float wv = __expf(ss[tt][tid] - mloc);
                wws[tt][tid] = wv;
                zadd += wv;
            }
            Z = Z * f + zadd;
            m = mloc;
            fct[tid] = f;
        }
        __syncthreads();
        // phase 2: rescale + accumulate weighted x rows
        float f = fct[h];
        #pragma unroll
        for (int k = 0; k < 16; ++k) y[k] *= f;
        #pragma unroll
        for (int tt = 0; tt < 8; ++tt) {
            float wv = wws[tt][h];
            const float4* xr = &xs4[tt * 256 + cs * 4];
            float4 a0 = xr[0], a1 = xr[1], a2 = xr[2], a3 = xr[3];
            y[0]  += wv * a0.x; y[1]  += wv * a0.y; y[2]  += wv * a0.z; y[3]  += wv * a0.w;
            y[4]  += wv * a1.x; y[5]  += wv * a1.y; y[6]  += wv * a1.z; y[7]  += wv * a1.w;
            y[8]  += wv * a2.x; y[9]  += wv * a2.y; y[10] += wv * a2.z; y[11] += wv * a2.w;
            y[12] += wv * a3.x; y[13] += wv * a3.y; y[14] += wv * a3.z; y[15] += wv * a3.w;
        }
    }

    int blk = b * 16 + chunk;
    float4* dst = (float4*)&g_party[(size_t)blk * 4096 + h * 1024 + cs * 16];
    dst[0] = make_float4(y[0],  y[1],  y[2],  y[3]);
    dst[1] = make_float4(y[4],  y[5],  y[6],  y[7]);
    dst[2] = make_float4(y[8],  y[9],  y[10], y[11]);
    dst[3] = make_float4(y[12], y[13], y[14], y[15]);
    if (tid < 4) {
        g_partm[blk * 4 + tid] = m;
        g_partz[blk * 4 + tid] = Z;
    }
}

// ---------------------------------------------------------------------------
// K_D: combine chunk partials + class-token term; output ybar = (sum att*x)/Z
// grid (4 heads, 8 batches), 256 threads
__global__ void k_combine(const float* __restrict__ tmp) {
    int h = blockIdx.x, b = blockIdx.y;
    int tid = threadIdx.x;
    __shared__ float red[8];
    __shared__ float s0_s;

    // s0 = tmp . wk_h   (scale already folded into wk)
    const float* wkh = g_wk + h * 1024;
    float pp = 0.f;
    #pragma unroll
    for (int k = 0; k < 4; ++k) pp += tmp[tid * 4 + k] * wkh[tid * 4 + k];
    pp += __shfl_xor_sync(0xffffffffu, pp, 1);
    pp += __shfl_xor_sync(0xffffffffu, pp, 2);
    pp += __shfl_xor_sync(0xffffffffu, pp, 4);
    pp += __shfl_xor_sync(0xffffffffu, pp, 8);
    pp += __shfl_xor_sync(0xffffffffu, pp, 16);
    int warp = tid >> 5, lane = tid & 31;
    if (lane == 0) red[warp] = pp;
    __syncthreads();
    if (tid == 0) {
        float s = 0.f;
        #pragma unroll
        for (int w = 0; w < 8; ++w) s += red[w];
        s0_s = s;
    }
    __syncthreads();
    float s0 = s0_s;

    float mv[16];
    float M = s0;
    #pragma unroll
    for (int i = 0; i < 16; ++i) {
        mv[i] = g_partm[(b * 16 + i) * 4 + h];
        M = fmaxf(M, mv[i]);
    }
    float e0 = __expf(s0 - M);
    float Zt = e0;
    float ef[16];
    #pragma unroll
    for (int i = 0; i < 16; ++i) {
        ef[i] = __expf(mv[i] - M);
        Zt += ef[i] * g_partz[(b * 16 + i) * 4 + h];
    }
    float inv = 1.f / Zt;

    const float4* tmp4 = (const float4*)tmp;
    float4 t4 = tmp4[tid];
    float ax = e0 * t4.x, ay = e0 * t4.y, az = e0 * t4.z, aw = e0 * t4.w;
    #pragma unroll
    for (int i = 0; i < 16; ++i) {
        const float4* py = (const float4*)&g_party[(size_t)((b * 16 + i) * 4 + h) * 1024];
        float4 v = py[tid];
        ax += ef[i] * v.x; ay += ef[i] * v.y; az += ef[i] * v.z; aw += ef[i] * v.w;
    }
    float4 outv = make_float4(ax * inv, ay * inv, az * inv, aw * inv);
    ((float4*)&g_ybar[(size_t)(b * 4 + h) * 1024])[tid] = outv;
}

// ---------------------------------------------------------------------------
// K_E: out0 partials: p1[cc][b][j] = sum_{c in chunk} ybar[b][j>>8][c] * Wqkv[c][2048+j]
// grid (4 j-blocks==heads, 8 c-chunks), 256 threads
__global__ void k_gemv1(const float* __restrict__ Wqkv) {
    int jblk = blockIdx.x;   // head
    int cc   = blockIdx.y;   // c-chunk of 128
    int tid  = threadIdx.x;
    __shared__ float ys[8][128];
    for (int i = tid; i < 1024; i += 256) {
        int bb = i >> 7, cr = i & 127;
        ys[bb][cr] = g_ybar[(size_t)(bb * 4 + jblk) * 1024 + cc * 128 + cr];
    }
    __syncthreads();
    int j = jblk * 256 + tid;
    float acc[8] = {0.f, 0.f, 0.f, 0.f, 0.f, 0.f, 0.f, 0.f};
    for (int cr = 0; cr < 128; ++cr) {
        float w = Wqkv[(size_t)(cc * 128 + cr) * 3072 + 2048 + j];
        #pragma unroll
        for (int bb = 0; bb < 8; ++bb) acc[bb] += ys[bb][cr] * w;
    }
    #pragma unroll
    for (int bb = 0; bb < 8; ++bb)
        g_p1[(size_t)(cc * 8 + bb) * 1024 + j] = acc[bb];
}

// ---------------------------------------------------------------------------
// K_F: final-proj partials, folding the p1 reduce + v-bias:
// out0[b][i] = bqkv[2048+i] + sum_cc p1[cc][b][i]
// p2[ic][b][j] = sum_{i in chunk} out0[b][i] * Wv[i][j]
// grid (4 j-blocks, 8 i-chunks), 256 threads
__global__ void k_gemv2(const float* __restrict__ Wv,
                        const float* __restrict__ bqkv) {
    int jblk = blockIdx.x;
    int ic   = blockIdx.y;
    int tid  = threadIdx.x;
    __shared__ float os[8][128];
    for (int idx = tid; idx < 1024; idx += 256) {
        int bb = idx >> 7, ir = idx & 127;
        int i = ic * 128 + ir;
        float v = bqkv[2048 + i];
        #pragma unroll
        for (int cc = 0; cc < 8; ++cc) v += g_p1[(size_t)(cc * 8 + bb) * 1024 + i];
        os[bb][ir] = v;
    }
    __syncthreads();
    int j = jblk * 256 + tid;
    float acc[8] = {0.f, 0.f, 0.f, 0.f, 0.f, 0.f, 0.f, 0.f};
    for (int ir = 0; ir < 128; ++ir) {
        float w = Wv[(size_t)(ic * 128 + ir) * 1024 + j];
        #pragma unroll
        for (int bb = 0; bb < 8; ++bb) acc[bb] += os[bb][ir] * w;
    }
    #pragma unroll
    for (int bb = 0; bb < 8; ++bb)
        g_p2[(size_t)(ic * 8 + bb) * 1024 + j] = acc[bb];
}

// ---------------------------------------------------------------------------
// K_G: reduce p2 + bv -> d_out [8,1024]
__global__ void k_final(const float* __restrict__ bv, float* __restrict__ out) {
    int idx = blockIdx.x * 256 + threadIdx.x;  // < 8192
    int bb = idx >> 10, j = idx & 1023;
    float v = bv[j];
    #pragma unroll
    for (int ic = 0; ic < 8; ++ic) v += g_p2[(size_t)(ic * 8 + bb) * 1024 + j];
    out[idx] = v;
}

// ---------------------------------------------------------------------------
extern "C" void kernel_launch(void* const* d_in, const int* in_sizes, int n_in,
                              void* d_out, int out_size) {
    const float* x    = (const float*)d_in[0];
    const float* tmp  = (const float*)d_in[1];
    const float* Wqkv = (const float*)d_in[2];
    const float* bqkv = (const float*)d_in[3];
    const float* Wv   = (const float*)d_in[4];
    const float* bv   = (const float*)d_in[5];

    k_q0_part<<<32, 256>>>(tmp, Wqkv);
    k_wk<<<128, 256>>>(Wqkv, bqkv);
    k_flash<<<dim3(16, 8), 256>>>(x);
    k_combine<<<dim3(4, 8), 256>>>(tmp);
    k_gemv1<<<dim3(4, 8), 256>>>(Wqkv);
    k_gemv2<<<dim3(4, 8), 256>>>(Wv, bqkv);
    k_final<<<32, 256>>>(bv, (float*)d_out);
}